// round 7
// baseline (speedup 1.0000x reference)
#include <cuda_runtime.h>
#include <cstddef>

// Fixed shapes: B=4, C=16, H=W=512
#define BB 4
#define CC 16
#define HH 512
#define WW 512
#define NN (HH * WW)
#define NPLANES (BB * CC)       // 64
#define E_CNT 2091012

#define TP 258                  // transpose smem pitch (conflict-free)

#define EDGE_BLOCKS 256         // 256 blocks x 8 warps = 2048 edge warps
#define TRANS_BLOCKS 4096       // 4096 blocks x 256 px
#define RY 4                    // rows per edge warp

// ---------------------------------------------------------------------------
// edge_start: analytic offset of node (h,w)'s first edge in reference order.
// ---------------------------------------------------------------------------
__device__ __forceinline__ int edge_start(int h, int w) {
    int R  = (h == 0) ? 0 : 2556 + (h - 1) * 4090;
    int vh = (h == 0 || h == HH - 1) ? 2 : 3;
    int Sv = (w == 0) ? 0 : 3 * w - 1;
    return R + vh * Sv - w;
}

// ---------------------------------------------------------------------------
// Per-pixel edge emission (both directions of each undirected pair).
// ---------------------------------------------------------------------------
__device__ __forceinline__ void emit_edges(int x, int y,
                                           float f0, float f1, float f2, float f3,
                                           float* __restrict__ eio,
                                           float2* __restrict__ attr) {
    const float SQ2 = 1.41421356237309515f;
    int p = (y << 9) | x;

    int Sp = edge_start(y, x);
    int posE  = ((y > 0) & (x > 0)) + (y > 0) + ((y > 0) & (x < WW - 1)) + (x > 0);
    int posSW = posE + (x < WW - 1);
    int posS  = posSW + ((y < HH - 1) & (x > 0));
    int posSE = posS + (y < HH - 1);

    float* ei_dst = eio + E_CNT;
    float fp = (float)p;

    if (x < WW - 1) {  // E ; reverse (0,-1) at (y, x+1)
        int q = p + 1;
        int er = edge_start(y, x + 1) + ((y > 0) ? (2 + (x < WW - 2)) : 0);
        int ef = Sp + posE;
        float2 a = make_float2(1.0f, f0);
        attr[ef] = a; attr[er] = a;
        eio[ef] = fp;        ei_dst[ef] = (float)q;
        eio[er] = (float)q;  ei_dst[er] = fp;
    }
    if (y < HH - 1 && x > 0) {  // SW ; reverse (-1,1) at (y+1, x-1)
        int q = p + WW - 1;
        int er = edge_start(y + 1, x - 1) + 1 + (x > 1);
        int ef = Sp + posSW;
        float2 a = make_float2(SQ2, f1);
        attr[ef] = a; attr[er] = a;
        eio[ef] = fp;        ei_dst[ef] = (float)q;
        eio[er] = (float)q;  ei_dst[er] = fp;
    }
    if (y < HH - 1) {  // S ; reverse (-1,0) at (y+1, x)
        int q = p + WW;
        int er = edge_start(y + 1, x) + (x > 0);
        int ef = Sp + posS;
        float2 a = make_float2(1.0f, f2);
        attr[ef] = a; attr[er] = a;
        eio[ef] = fp;        ei_dst[ef] = (float)q;
        eio[er] = (float)q;  ei_dst[er] = fp;
    }
    if (y < HH - 1 && x < WW - 1) {  // SE ; reverse (-1,-1) at (y+1, x+1)
        int q = p + WW + 1;
        int er = edge_start(y + 1, x + 1);
        int ef = Sp + posSE;
        float2 a = make_float2(SQ2, f3);
        attr[ef] = a; attr[er] = a;
        eio[ef] = fp;        ei_dst[ef] = (float)q;
        eio[er] = (float)q;  ei_dst[er] = fp;
    }
}

// ---------------------------------------------------------------------------
// Edge role: warp = 32 cols x 4 rows. Each plane processed completely
// (5 rows loaded, diffs accumulated, rows discarded) -> tiny register
// footprint, PF=2 planes per iteration for MLP. No smem, no barriers.
// ---------------------------------------------------------------------------
__device__ __forceinline__ void edge_role(int eb, int tid,
                                          const float* __restrict__ grid,
                                          float* __restrict__ eio,
                                          float2* __restrict__ attr) {
    const unsigned FULL = 0xffffffffu;
    int warp = eb * 8 + (tid >> 5);
    int lane = tid & 31;

    int cchunk = warp & 15;          // 16 column chunks
    int rchunk = warp >> 4;          // 128 row chunks
    int cx = cchunk * 32;
    int y0 = rchunk * RY;
    int x  = cx + lane;

    bool isL = (lane == 0), isR = (lane == 31);
    bool bl  = isL || isR;
    int xb   = isL ? max(cx - 1, 0) : min(cx + 32, WW - 1);

    int ro[RY + 1];
#pragma unroll
    for (int r = 0; r <= RY; r++) ro[r] = min(y0 + r, HH - 1) * WW;

    float aE[RY], aSW[RY], aS[RY], aSE[RY];
#pragma unroll
    for (int r = 0; r < RY; r++) { aE[r] = aSW[r] = aS[r] = aSE[r] = 0.f; }

    for (int g = 0; g < NPLANES / 2; g++) {
        const float* pl0 = grid + (size_t)(2 * g) * NN;
        const float* pl1 = pl0 + NN;

        float t0[RY + 1], t1[RY + 1], b0[RY + 1], b1[RY + 1];
#pragma unroll
        for (int r = 0; r <= RY; r++) {
            t0[r] = pl0[ro[r] + x];
            t1[r] = pl1[ro[r] + x];
            if (bl) { b0[r] = pl0[ro[r] + xb]; b1[r] = pl1[ro[r] + xb]; }
        }

#pragma unroll
        for (int r = 0; r < RY; r++) {
            // plane 0
            {
                float cv = t0[r], nv = t0[r + 1];
                float ec = __shfl_down_sync(FULL, cv, 1); if (isR) ec = b0[r];
                float su = __shfl_up_sync(FULL, nv, 1);   if (isL) su = b0[r + 1];
                float sd = __shfl_down_sync(FULL, nv, 1); if (isR) sd = b0[r + 1];
                aE[r]  += fabsf(cv - ec);
                aSW[r] += fabsf(cv - su);
                aS[r]  += fabsf(cv - nv);
                aSE[r] += fabsf(cv - sd);
            }
            // plane 1
            {
                float cv = t1[r], nv = t1[r + 1];
                float ec = __shfl_down_sync(FULL, cv, 1); if (isR) ec = b1[r];
                float su = __shfl_up_sync(FULL, nv, 1);   if (isL) su = b1[r + 1];
                float sd = __shfl_down_sync(FULL, nv, 1); if (isR) sd = b1[r + 1];
                aE[r]  += fabsf(cv - ec);
                aSW[r] += fabsf(cv - su);
                aS[r]  += fabsf(cv - nv);
                aSE[r] += fabsf(cv - sd);
            }
        }
    }

    const float inv = 1.0f / (float)NPLANES;
#pragma unroll
    for (int r = 0; r < RY; r++)
        emit_edges(x, y0 + r, aE[r] * inv, aSW[r] * inv, aS[r] * inv, aSE[r] * inv,
                   eio, attr);
}

// ---------------------------------------------------------------------------
// Transpose role: NCHW -> (B*H*W, C) via smem staging, fully coalesced.
// ---------------------------------------------------------------------------
__device__ __forceinline__ void trans_role(int tb, int t, float* s,
                                           const float* __restrict__ in,
                                           float* __restrict__ out) {
    int b  = tb >> 10;                 // 1024 blocks per batch image
    int p0 = (tb & 1023) * 256;

    const float* src = in + (size_t)b * CC * NN + p0 + t;
#pragma unroll
    for (int c = 0; c < CC; c++)
        s[c * TP + t] = src[(size_t)c * NN];
    __syncthreads();

    float4* o = (float4*)(out + ((size_t)b * NN + p0) * CC);
    int ch = (t & 3) * 4;
#pragma unroll
    for (int i = 0; i < 4; i++) {
        int px = i * 64 + (t >> 2);
        o[i * 256 + t] = make_float4(s[(ch + 0) * TP + px],
                                     s[(ch + 1) * TP + px],
                                     s[(ch + 2) * TP + px],
                                     s[(ch + 3) * TP + px]);
    }
}

// ---------------------------------------------------------------------------
// Fused kernel: edge blocks first (long-running), transpose blocks fill in.
// Both stream the same 64MB grid -> L2 reuse between roles.
// ---------------------------------------------------------------------------
__global__ void __launch_bounds__(256) fused_kernel(const float* __restrict__ grid,
                                                    float* __restrict__ nf,
                                                    float* __restrict__ eio,
                                                    float2* __restrict__ attr) {
    __shared__ float s[CC * TP];
    int bid = blockIdx.x;
    int t = threadIdx.x;

    if (bid < EDGE_BLOCKS) {
        edge_role(bid, t, grid, eio, attr);
    } else {
        trans_role(bid - EDGE_BLOCKS, t, s, grid, nf);
    }
}

// ---------------------------------------------------------------------------
extern "C" void kernel_launch(void* const* d_in, const int* in_sizes, int n_in,
                              void* d_out, int out_size) {
    const float* grid = (const float*)d_in[0];

    float* out   = (float*)d_out;
    float* nf    = out;
    float* eio   = out + (size_t)BB * NN * CC;
    float2* attr = (float2*)(eio + 2 * E_CNT);

    fused_kernel<<<EDGE_BLOCKS + TRANS_BLOCKS, 256>>>(grid, nf, eio, attr);
}

// round 8
// speedup vs baseline: 1.2294x; 1.2294x over previous
#include <cuda_runtime.h>
#include <cstddef>

// Fixed shapes: B=4, C=16, H=W=512
#define BB 4
#define CC 16
#define HH 512
#define WW 512
#define NN (HH * WW)
#define NPLANES (BB * CC)       // 64
#define E_CNT 2091012

#define TP 258                  // transpose smem pitch (conflict-free)

// 4 MB scratch: forward-direction mean diffs, [dir][y][x], dir: 0=E,1=SW,2=S,3=SE
__device__ float g_scratch[4 * NN];

// ---------------------------------------------------------------------------
// Kernel 1: NCHW -> (B*H*W, C) via smem staging. Coalesced loads AND stores.
// ---------------------------------------------------------------------------
__global__ void __launch_bounds__(256) transpose_kernel(const float* __restrict__ in,
                                                        float* __restrict__ out) {
    __shared__ float s[CC * TP];

    int t  = threadIdx.x;
    int p0 = blockIdx.x * 256;
    int b  = blockIdx.y;

    const float* src = in + (size_t)b * CC * NN + p0 + t;
#pragma unroll
    for (int c = 0; c < CC; c++)
        s[c * TP + t] = src[(size_t)c * NN];
    __syncthreads();

    float4* o = (float4*)(out + ((size_t)b * NN + p0) * CC);
    int ch = (t & 3) * 4;
#pragma unroll
    for (int i = 0; i < 4; i++) {
        int px = i * 64 + (t >> 2);
        o[i * 256 + t] = make_float4(s[(ch + 0) * TP + px],
                                     s[(ch + 1) * TP + px],
                                     s[(ch + 2) * TP + px],
                                     s[(ch + 3) * TP + px]);
    }
}

// ---------------------------------------------------------------------------
// Phase A: forward diffs (E, SW, S, SE) per pixel, mean over 64 planes,
// written DENSE to g_scratch. Warp = 64 cols (float2 lanes) x 4 rows.
// 5 rows loaded per plane, 2 planes in flight, x+-1 via shuffles.
// ---------------------------------------------------------------------------
__global__ void __launch_bounds__(128) phaseA_kernel(const float* __restrict__ grid) {
    const unsigned FULL = 0xffffffffu;
    int warp = blockIdx.x * 4 + (threadIdx.x >> 5);
    int lane = threadIdx.x & 31;

    int cchunk = warp & 7;           // 8 chunks of 64 cols
    int rchunk = warp >> 3;          // 128 chunks of 4 rows
    int cx = cchunk * 64;
    int y0 = rchunk * 4;
    int x0 = cx + lane * 2;

    bool isL = (lane == 0), isR = (lane == 31);
    bool bl  = isL || isR;
    int xb   = isL ? max(cx - 1, 0) : min(cx + 64, WW - 1);

    int ro[5];
#pragma unroll
    for (int j = 0; j < 5; j++) ro[j] = min(y0 + j, HH - 1) * WW;

    float2 aE[4], aSW[4], aS[4], aSE[4];
#pragma unroll
    for (int r = 0; r < 4; r++) {
        aE[r] = aSW[r] = aS[r] = aSE[r] = make_float2(0.f, 0.f);
    }

    for (int g = 0; g < NPLANES / 2; g++) {
        const float* p0 = grid + (size_t)(2 * g) * NN;
        const float* p1 = p0 + NN;

        float2 a0[5], a1[5];
        float  b0[5], b1[5];
#pragma unroll
        for (int j = 0; j < 5; j++) {
            a0[j] = *(const float2*)(p0 + ro[j] + x0);
            a1[j] = *(const float2*)(p1 + ro[j] + x0);
        }
#pragma unroll
        for (int j = 0; j < 5; j++) {
            if (bl) { b0[j] = p0[ro[j] + xb]; b1[j] = p1[ro[j] + xb]; }
        }

#pragma unroll
        for (int pp = 0; pp < 2; pp++) {
            float2* a = pp ? a1 : a0;
            float*  b = pp ? b1 : b0;

            float L[5], R[5];
#pragma unroll
            for (int j = 0; j < 5; j++) {
                R[j] = __shfl_down_sync(FULL, a[j].x, 1);
                L[j] = __shfl_up_sync(FULL, a[j].y, 1);
                if (isR) R[j] = b[j];
                if (isL) L[j] = b[j];
            }
#pragma unroll
            for (int r = 0; r < 4; r++) {
                float c0 = a[r].x, c1 = a[r].y;
                float n0 = a[r + 1].x, n1 = a[r + 1].y;
                aE[r].x  += fabsf(c0 - c1);
                aE[r].y  += fabsf(c1 - R[r]);
                aSW[r].x += fabsf(c0 - L[r + 1]);
                aSW[r].y += fabsf(c1 - n0);
                aS[r].x  += fabsf(c0 - n0);
                aS[r].y  += fabsf(c1 - n1);
                aSE[r].x += fabsf(c0 - n1);
                aSE[r].y += fabsf(c1 - R[r + 1]);
            }
        }
    }

    const float inv = 1.0f / (float)NPLANES;
#pragma unroll
    for (int r = 0; r < 4; r++) {
        int o = (y0 + r) * WW + x0;
        *(float2*)(g_scratch + 0 * NN + o) = make_float2(aE[r].x * inv,  aE[r].y * inv);
        *(float2*)(g_scratch + 1 * NN + o) = make_float2(aSW[r].x * inv, aSW[r].y * inv);
        *(float2*)(g_scratch + 2 * NN + o) = make_float2(aS[r].x * inv,  aS[r].y * inv);
        *(float2*)(g_scratch + 3 * NN + o) = make_float2(aSE[r].x * inv, aSE[r].y * inv);
    }
}

// ---------------------------------------------------------------------------
// Phase B: edge-major emission. One thread per directed edge slot; block
// row = y (grid.y), o = slot within row. Slot -> (x, dir) via analytic
// inversion + packed nibble LUTs. All output stores perfectly dense.
// ---------------------------------------------------------------------------
__global__ void __launch_bounds__(1024) phaseB_kernel(float* __restrict__ eio,
                                                      float2* __restrict__ attr) {
    int y = blockIdx.y;
    int o = blockIdx.x * 1024 + threadIdx.x;

    bool top = (y == 0), bot = (y == HH - 1);
    int rowcnt = (top || bot) ? 2556 : 4090;
    if (o >= rowcnt) return;
    int base = top ? 0 : 2556 + (y - 1) * 4090;

    int x, kk;
    unsigned lut;
    if (top || bot) {
        x = (o < 3) ? 0 : (o + 2) / 5;
        int ps = (x == 0) ? 0 : 5 * x - 2;
        kk = o - ps;
        if (top) lut = (x == 0) ? 0x764u : (x == WW - 1) ? 0x653u : 0x76543u;
        else     lut = (x == 0) ? 0x421u : (x == WW - 1) ? 0x310u : 0x43210u;
    } else {
        x = min((o + 3) >> 3, WW - 1);
        int ps = (x == 0) ? 0 : 8 * x - 3;
        kk = o - ps;
        lut = (x == 0) ? 0x76421u : (x == WW - 1) ? 0x65310u : 0x76543210u;
    }

    int dir = (lut >> (4 * kk)) & 0xF;          // _OFFSETS index 0..7
    int k2  = dir + (dir >= 4);                 // 0..8 grid position
    int dh  = k2 / 3 - 1;
    int dw  = k2 - (dh + 1) * 3 - 1;

    int p = y * WW + x;
    int q = p + dh * WW + dw;
    float dist = (dh * dw != 0) ? 1.41421356237309515f : 1.0f;

    // forward dirs read own pixel's array; backward read opposite dir at q
    int arr = (dir >= 4) ? (dir - 4) : (3 - dir);
    int loc = (dir >= 4) ? p : q;
    float f = g_scratch[arr * NN + loc];

    int e = base + o;
    eio[e]         = (float)p;
    eio[E_CNT + e] = (float)q;
    attr[e] = make_float2(dist, f);
}

// ---------------------------------------------------------------------------
extern "C" void kernel_launch(void* const* d_in, const int* in_sizes, int n_in,
                              void* d_out, int out_size) {
    const float* grid = (const float*)d_in[0];

    float* out   = (float*)d_out;
    float* nf    = out;
    float* eio   = out + (size_t)BB * NN * CC;
    float2* attr = (float2*)(eio + 2 * E_CNT);

    phaseA_kernel<<<256, 128>>>(grid);                        // 1024 warps
    transpose_kernel<<<dim3(NN / 256, BB), 256>>>(grid, nf);
    phaseB_kernel<<<dim3(4, HH), 1024>>>(eio, attr);
}

// round 10
// speedup vs baseline: 1.3413x; 1.0911x over previous
#include <cuda_runtime.h>
#include <cstddef>

// Fixed shapes: B=4, C=16, H=W=512
#define BB 4
#define CC 16
#define HH 512
#define WW 512
#define NN (HH * WW)
#define NPLANES (BB * CC)       // 64
#define E_CNT 2091012

#define TP 258                  // transpose smem pitch (conflict-free)

#define NSEG 4                  // plane-loop split factor
#define PLANES_PER_SEG (NPLANES / NSEG)   // 16

// 16 MB scratch: [seg][dir][y][x], dir: 0=E,1=SW,2=S,3=SE (pre-scaled by 1/64)
__device__ float g_scratch[NSEG * 4 * NN];

// ---------------------------------------------------------------------------
// Kernel 1: NCHW -> (B*H*W, C) via smem staging. Coalesced loads AND stores.
// ---------------------------------------------------------------------------
__global__ void __launch_bounds__(256) transpose_kernel(const float* __restrict__ in,
                                                        float* __restrict__ out) {
    __shared__ float s[CC * TP];

    int t  = threadIdx.x;
    int p0 = blockIdx.x * 256;
    int b  = blockIdx.y;

    const float* src = in + (size_t)b * CC * NN + p0 + t;
#pragma unroll
    for (int c = 0; c < CC; c++)
        s[c * TP + t] = src[(size_t)c * NN];
    __syncthreads();

    float4* o = (float4*)(out + ((size_t)b * NN + p0) * CC);
    int ch = (t & 3) * 4;
#pragma unroll
    for (int i = 0; i < 4; i++) {
        int px = i * 64 + (t >> 2);
        o[i * 256 + t] = make_float4(s[(ch + 0) * TP + px],
                                     s[(ch + 1) * TP + px],
                                     s[(ch + 2) * TP + px],
                                     s[(ch + 3) * TP + px]);
    }
}

// ---------------------------------------------------------------------------
// Phase A: forward diffs (E, SW, S, SE) per pixel over 16 planes (seg =
// blockIdx.y), written DENSE to this segment's scratch. Warp = 64 cols
// (float2 lanes) x 4 rows; 5 rows per plane, 2 planes in flight.
// ---------------------------------------------------------------------------
__global__ void __launch_bounds__(128) phaseA_kernel(const float* __restrict__ grid) {
    const unsigned FULL = 0xffffffffu;
    int warp = blockIdx.x * 4 + (threadIdx.x >> 5);
    int lane = threadIdx.x & 31;
    int seg  = blockIdx.y;

    int cchunk = warp & 7;           // 8 chunks of 64 cols
    int rchunk = warp >> 3;          // 128 chunks of 4 rows
    int cx = cchunk * 64;
    int y0 = rchunk * 4;
    int x0 = cx + lane * 2;

    bool isL = (lane == 0), isR = (lane == 31);
    bool bl  = isL || isR;
    int xb   = isL ? max(cx - 1, 0) : min(cx + 64, WW - 1);

    int ro[5];
#pragma unroll
    for (int j = 0; j < 5; j++) ro[j] = min(y0 + j, HH - 1) * WW;

    float2 aE[4], aSW[4], aS[4], aSE[4];
#pragma unroll
    for (int r = 0; r < 4; r++) {
        aE[r] = aSW[r] = aS[r] = aSE[r] = make_float2(0.f, 0.f);
    }

    const float* gseg = grid + (size_t)seg * PLANES_PER_SEG * NN;

    for (int g = 0; g < PLANES_PER_SEG / 2; g++) {
        const float* p0 = gseg + (size_t)(2 * g) * NN;
        const float* p1 = p0 + NN;

        float2 a0[5], a1[5];
        float  b0[5], b1[5];
#pragma unroll
        for (int j = 0; j < 5; j++) {
            a0[j] = *(const float2*)(p0 + ro[j] + x0);
            a1[j] = *(const float2*)(p1 + ro[j] + x0);
        }
#pragma unroll
        for (int j = 0; j < 5; j++) {
            if (bl) { b0[j] = p0[ro[j] + xb]; b1[j] = p1[ro[j] + xb]; }
        }

#pragma unroll
        for (int pp = 0; pp < 2; pp++) {
            float2* a = pp ? a1 : a0;
            float*  b = pp ? b1 : b0;

            float L[5], R[5];
#pragma unroll
            for (int j = 0; j < 5; j++) {
                R[j] = __shfl_down_sync(FULL, a[j].x, 1);
                L[j] = __shfl_up_sync(FULL, a[j].y, 1);
                if (isR) R[j] = b[j];
                if (isL) L[j] = b[j];
            }
#pragma unroll
            for (int r = 0; r < 4; r++) {
                float c0 = a[r].x, c1 = a[r].y;
                float n0 = a[r + 1].x, n1 = a[r + 1].y;
                aE[r].x  += fabsf(c0 - c1);
                aE[r].y  += fabsf(c1 - R[r]);
                aSW[r].x += fabsf(c0 - L[r + 1]);
                aSW[r].y += fabsf(c1 - n0);
                aS[r].x  += fabsf(c0 - n0);
                aS[r].y  += fabsf(c1 - n1);
                aSE[r].x += fabsf(c0 - n1);
                aSE[r].y += fabsf(c1 - R[r + 1]);
            }
        }
    }

    const float inv = 1.0f / (float)NPLANES;
    float* sc = g_scratch + (size_t)seg * 4 * NN;
#pragma unroll
    for (int r = 0; r < 4; r++) {
        int o = (y0 + r) * WW + x0;
        *(float2*)(sc + 0 * NN + o) = make_float2(aE[r].x * inv,  aE[r].y * inv);
        *(float2*)(sc + 1 * NN + o) = make_float2(aSW[r].x * inv, aSW[r].y * inv);
        *(float2*)(sc + 2 * NN + o) = make_float2(aS[r].x * inv,  aS[r].y * inv);
        *(float2*)(sc + 3 * NN + o) = make_float2(aSE[r].x * inv, aSE[r].y * inv);
    }
}

// ---------------------------------------------------------------------------
// Phase B: edge-major emission. One thread per directed edge slot; block
// row = y (grid.y), o = slot within row. Slot -> (x, dir) via analytic
// inversion + packed nibble LUTs. Sums the NSEG scratch segments.
// All output stores perfectly dense.
// ---------------------------------------------------------------------------
__global__ void __launch_bounds__(1024) phaseB_kernel(float* __restrict__ eio,
                                                      float2* __restrict__ attr) {
    int y = blockIdx.y;
    int o = blockIdx.x * 1024 + threadIdx.x;

    bool top = (y == 0), bot = (y == HH - 1);
    int rowcnt = (top || bot) ? 2556 : 4090;
    if (o >= rowcnt) return;
    int base = top ? 0 : 2556 + (y - 1) * 4090;

    int x, kk;
    unsigned lut;
    if (top || bot) {
        x = (o < 3) ? 0 : (o + 2) / 5;
        int ps = (x == 0) ? 0 : 5 * x - 2;
        kk = o - ps;
        if (top) lut = (x == 0) ? 0x764u : (x == WW - 1) ? 0x653u : 0x76543u;
        else     lut = (x == 0) ? 0x421u : (x == WW - 1) ? 0x310u : 0x43210u;
    } else {
        x = min((o + 3) >> 3, WW - 1);
        int ps = (x == 0) ? 0 : 8 * x - 3;
        kk = o - ps;
        lut = (x == 0) ? 0x76421u : (x == WW - 1) ? 0x65310u : 0x76543210u;
    }

    int dir = (lut >> (4 * kk)) & 0xF;          // _OFFSETS index 0..7
    int k2  = dir + (dir >= 4);                 // 0..8 grid position
    int dh  = k2 / 3 - 1;
    int dw  = k2 - (dh + 1) * 3 - 1;

    int p = y * WW + x;
    int q = p + dh * WW + dw;
    float dist = (dh * dw != 0) ? 1.41421356237309515f : 1.0f;

    // forward dirs read own pixel's array; backward read opposite dir at q
    int arr = (dir >= 4) ? (dir - 4) : (3 - dir);
    int loc = (dir >= 4) ? p : q;

    float f = 0.f;
#pragma unroll
    for (int s = 0; s < NSEG; s++)
        f += g_scratch[(size_t)s * 4 * NN + arr * NN + loc];

    int e = base + o;
    eio[e]         = (float)p;
    eio[E_CNT + e] = (float)q;
    attr[e] = make_float2(dist, f);
}

// ---------------------------------------------------------------------------
extern "C" void kernel_launch(void* const* d_in, const int* in_sizes, int n_in,
                              void* d_out, int out_size) {
    const float* grid = (const float*)d_in[0];

    float* out   = (float*)d_out;
    float* nf    = out;
    float* eio   = out + (size_t)BB * NN * CC;
    float2* attr = (float2*)(eio + 2 * E_CNT);

    phaseA_kernel<<<dim3(256, NSEG), 128>>>(grid);            // 4096 warps
    transpose_kernel<<<dim3(NN / 256, BB), 256>>>(grid, nf);
    phaseB_kernel<<<dim3(4, HH), 1024>>>(eio, attr);
}

// round 11
// speedup vs baseline: 1.4698x; 1.0958x over previous
#include <cuda_runtime.h>
#include <cstddef>

// Fixed shapes: B=4, C=16, H=W=512
#define BB 4
#define CC 16
#define HH 512
#define WW 512
#define NN (HH * WW)
#define NPLANES (BB * CC)       // 64
#define E_CNT 2091012

#define TP 258                  // transpose smem pitch (conflict-free)

#define NSEG 4                  // plane-loop split factor
#define PLANES_PER_SEG (NPLANES / NSEG)   // 16

#define TRANS_BLOCKS 4096       // 4096 blocks x 256 px (b = tb>>10)
#define B_BLOCKS_PER_ROW 16     // 16 x 256 = 4096 >= 4090 slots/row

// 16 MB scratch: [seg][dir][y][x], dir: 0=E,1=SW,2=S,3=SE (pre-scaled by 1/64)
__device__ float g_scratch[NSEG * 4 * NN];

// ---------------------------------------------------------------------------
// Phase A: forward diffs (E, SW, S, SE) per pixel over 16 planes (seg =
// blockIdx.y), written DENSE to this segment's scratch. Warp = 64 cols
// (float2 lanes) x 4 rows; 5 rows per plane, 2 planes in flight.
// ---------------------------------------------------------------------------
__global__ void __launch_bounds__(128) phaseA_kernel(const float* __restrict__ grid) {
    const unsigned FULL = 0xffffffffu;
    int warp = blockIdx.x * 4 + (threadIdx.x >> 5);
    int lane = threadIdx.x & 31;
    int seg  = blockIdx.y;

    int cchunk = warp & 7;           // 8 chunks of 64 cols
    int rchunk = warp >> 3;          // 128 chunks of 4 rows
    int cx = cchunk * 64;
    int y0 = rchunk * 4;
    int x0 = cx + lane * 2;

    bool isL = (lane == 0), isR = (lane == 31);
    bool bl  = isL || isR;
    int xb   = isL ? max(cx - 1, 0) : min(cx + 64, WW - 1);

    int ro[5];
#pragma unroll
    for (int j = 0; j < 5; j++) ro[j] = min(y0 + j, HH - 1) * WW;

    float2 aE[4], aSW[4], aS[4], aSE[4];
#pragma unroll
    for (int r = 0; r < 4; r++) {
        aE[r] = aSW[r] = aS[r] = aSE[r] = make_float2(0.f, 0.f);
    }

    const float* gseg = grid + (size_t)seg * PLANES_PER_SEG * NN;

    for (int g = 0; g < PLANES_PER_SEG / 2; g++) {
        const float* p0 = gseg + (size_t)(2 * g) * NN;
        const float* p1 = p0 + NN;

        float2 a0[5], a1[5];
        float  b0[5], b1[5];
#pragma unroll
        for (int j = 0; j < 5; j++) {
            a0[j] = *(const float2*)(p0 + ro[j] + x0);
            a1[j] = *(const float2*)(p1 + ro[j] + x0);
        }
#pragma unroll
        for (int j = 0; j < 5; j++) {
            if (bl) { b0[j] = p0[ro[j] + xb]; b1[j] = p1[ro[j] + xb]; }
        }

#pragma unroll
        for (int pp = 0; pp < 2; pp++) {
            float2* a = pp ? a1 : a0;
            float*  b = pp ? b1 : b0;

            float L[5], R[5];
#pragma unroll
            for (int j = 0; j < 5; j++) {
                R[j] = __shfl_down_sync(FULL, a[j].x, 1);
                L[j] = __shfl_up_sync(FULL, a[j].y, 1);
                if (isR) R[j] = b[j];
                if (isL) L[j] = b[j];
            }
#pragma unroll
            for (int r = 0; r < 4; r++) {
                float c0 = a[r].x, c1 = a[r].y;
                float n0 = a[r + 1].x, n1 = a[r + 1].y;
                aE[r].x  += fabsf(c0 - c1);
                aE[r].y  += fabsf(c1 - R[r]);
                aSW[r].x += fabsf(c0 - L[r + 1]);
                aSW[r].y += fabsf(c1 - n0);
                aS[r].x  += fabsf(c0 - n0);
                aS[r].y  += fabsf(c1 - n1);
                aSE[r].x += fabsf(c0 - n1);
                aSE[r].y += fabsf(c1 - R[r + 1]);
            }
        }
    }

    const float inv = 1.0f / (float)NPLANES;
    float* sc = g_scratch + (size_t)seg * 4 * NN;
#pragma unroll
    for (int r = 0; r < 4; r++) {
        int o = (y0 + r) * WW + x0;
        *(float2*)(sc + 0 * NN + o) = make_float2(aE[r].x * inv,  aE[r].y * inv);
        *(float2*)(sc + 1 * NN + o) = make_float2(aSW[r].x * inv, aSW[r].y * inv);
        *(float2*)(sc + 2 * NN + o) = make_float2(aS[r].x * inv,  aS[r].y * inv);
        *(float2*)(sc + 3 * NN + o) = make_float2(aSE[r].x * inv, aSE[r].y * inv);
    }
}

// ---------------------------------------------------------------------------
// Transpose role: NCHW -> (B*H*W, C) via smem staging, fully coalesced.
// ---------------------------------------------------------------------------
__device__ __forceinline__ void trans_role(int tb, int t, float* s,
                                           const float* __restrict__ in,
                                           float* __restrict__ out) {
    int b  = tb >> 10;                 // 1024 blocks per batch image
    int p0 = (tb & 1023) * 256;

    const float* src = in + (size_t)b * CC * NN + p0 + t;
#pragma unroll
    for (int c = 0; c < CC; c++)
        s[c * TP + t] = src[(size_t)c * NN];
    __syncthreads();

    float4* o = (float4*)(out + ((size_t)b * NN + p0) * CC);
    int ch = (t & 3) * 4;
#pragma unroll
    for (int i = 0; i < 4; i++) {
        int px = i * 64 + (t >> 2);
        o[i * 256 + t] = make_float4(s[(ch + 0) * TP + px],
                                     s[(ch + 1) * TP + px],
                                     s[(ch + 2) * TP + px],
                                     s[(ch + 3) * TP + px]);
    }
}

// ---------------------------------------------------------------------------
// Phase B role: edge-major emission, one thread per directed edge slot.
// Slot -> (x, dir) via analytic inversion + packed nibble LUTs. Sums the
// NSEG scratch segments. All output stores perfectly dense.
// ---------------------------------------------------------------------------
__device__ __forceinline__ void phaseB_role(int bb, int t,
                                            float* __restrict__ eio,
                                            float2* __restrict__ attr) {
    int y = bb >> 4;                            // 16 blocks per row
    int o = (bb & 15) * 256 + t;

    bool top = (y == 0), bot = (y == HH - 1);
    int rowcnt = (top || bot) ? 2556 : 4090;
    if (o >= rowcnt) return;
    int base = top ? 0 : 2556 + (y - 1) * 4090;

    int x, kk;
    unsigned lut;
    if (top || bot) {
        x = (o < 3) ? 0 : (o + 2) / 5;
        int ps = (x == 0) ? 0 : 5 * x - 2;
        kk = o - ps;
        if (top) lut = (x == 0) ? 0x764u : (x == WW - 1) ? 0x653u : 0x76543u;
        else     lut = (x == 0) ? 0x421u : (x == WW - 1) ? 0x310u : 0x43210u;
    } else {
        x = min((o + 3) >> 3, WW - 1);
        int ps = (x == 0) ? 0 : 8 * x - 3;
        kk = o - ps;
        lut = (x == 0) ? 0x76421u : (x == WW - 1) ? 0x65310u : 0x76543210u;
    }

    int dir = (lut >> (4 * kk)) & 0xF;          // _OFFSETS index 0..7
    int k2  = dir + (dir >= 4);                 // 0..8 grid position
    int dh  = k2 / 3 - 1;
    int dw  = k2 - (dh + 1) * 3 - 1;

    int p = y * WW + x;
    int q = p + dh * WW + dw;
    float dist = (dh * dw != 0) ? 1.41421356237309515f : 1.0f;

    // forward dirs read own pixel's array; backward read opposite dir at q
    int arr = (dir >= 4) ? (dir - 4) : (3 - dir);
    int loc = (dir >= 4) ? p : q;

    float f = 0.f;
#pragma unroll
    for (int s = 0; s < NSEG; s++)
        f += g_scratch[(size_t)s * 4 * NN + arr * NN + loc];

    int e = base + o;
    eio[e]         = (float)p;
    eio[E_CNT + e] = (float)q;
    attr[e] = make_float2(dist, f);
}

// ---------------------------------------------------------------------------
// Fused transpose + phaseB: both independent of each other, both run after
// phaseA. Co-executing overlaps T's store-heavy phases with B's L2 reads.
// ---------------------------------------------------------------------------
__global__ void __launch_bounds__(256) fusedTB_kernel(const float* __restrict__ grid,
                                                      float* __restrict__ nf,
                                                      float* __restrict__ eio,
                                                      float2* __restrict__ attr) {
    __shared__ float s[CC * TP];
    int bid = blockIdx.x;
    int t = threadIdx.x;

    if (bid < TRANS_BLOCKS) {
        trans_role(bid, t, s, grid, nf);
    } else {
        phaseB_role(bid - TRANS_BLOCKS, t, eio, attr);
    }
}

// ---------------------------------------------------------------------------
extern "C" void kernel_launch(void* const* d_in, const int* in_sizes, int n_in,
                              void* d_out, int out_size) {
    const float* grid = (const float*)d_in[0];

    float* out   = (float*)d_out;
    float* nf    = out;
    float* eio   = out + (size_t)BB * NN * CC;
    float2* attr = (float2*)(eio + 2 * E_CNT);

    phaseA_kernel<<<dim3(256, NSEG), 128>>>(grid);            // 4096 warps
    fusedTB_kernel<<<TRANS_BLOCKS + HH * B_BLOCKS_PER_ROW, 256>>>(grid, nf, eio, attr);
}

// round 12
// speedup vs baseline: 1.5826x; 1.0767x over previous
#include <cuda_runtime.h>
#include <cstddef>

// Fixed shapes: B=4, C=16, H=W=512
#define BB 4
#define CC 16
#define HH 512
#define WW 512
#define NN (HH * WW)
#define NPLANES (BB * CC)       // 64
#define E_CNT 2091012

#define TP 258                  // transpose smem pitch (conflict-free)

#define NSEG 4
#define PLANES_PER_SEG (NPLANES / NSEG)   // 16

#define A_BLOCKS_PER_SEG 128    // 128 blocks x 8 warps = 1024 warps per seg
#define A_BLOCKS (NSEG * A_BLOCKS_PER_SEG)   // 512
#define TRANS_BLOCKS 4096

// 16 MB scratch: [seg][dir][y][x], dir: 0=E,1=SW,2=S,3=SE (pre-scaled by 1/64)
__device__ float g_scratch[NSEG * 4 * NN];

// ---------------------------------------------------------------------------
// Phase A role: forward diffs (E, SW, S, SE) per pixel over this segment's
// 16 planes, written DENSE to scratch. Warp = 64 cols (float2 lanes) x 4
// rows; 5 rows per plane, 1 plane per iteration (10 independent LDGs).
// ---------------------------------------------------------------------------
__device__ __forceinline__ void phaseA_role(int ab, int tid,
                                            const float* __restrict__ grid) {
    const unsigned FULL = 0xffffffffu;
    int lane = tid & 31;
    int seg  = ab >> 7;                       // 128 blocks per seg
    int warp = (ab & 127) * 8 + (tid >> 5);   // 0..1023 within seg

    int cchunk = warp & 7;           // 8 chunks of 64 cols
    int rchunk = warp >> 3;          // 128 chunks of 4 rows
    int cx = cchunk * 64;
    int y0 = rchunk * 4;
    int x0 = cx + lane * 2;

    bool isL = (lane == 0), isR = (lane == 31);
    bool bl  = isL || isR;
    int xb   = isL ? max(cx - 1, 0) : min(cx + 64, WW - 1);

    int ro[5];
#pragma unroll
    for (int j = 0; j < 5; j++) ro[j] = min(y0 + j, HH - 1) * WW;

    float2 aE[4], aSW[4], aS[4], aSE[4];
#pragma unroll
    for (int r = 0; r < 4; r++) {
        aE[r] = aSW[r] = aS[r] = aSE[r] = make_float2(0.f, 0.f);
    }

    const float* gseg = grid + (size_t)seg * PLANES_PER_SEG * NN;

    for (int g = 0; g < PLANES_PER_SEG; g++) {
        const float* p0 = gseg + (size_t)g * NN;

        float2 a[5];
        float  b[5];
#pragma unroll
        for (int j = 0; j < 5; j++)
            a[j] = *(const float2*)(p0 + ro[j] + x0);
#pragma unroll
        for (int j = 0; j < 5; j++)
            if (bl) b[j] = p0[ro[j] + xb];

        float L[5], R[5];
#pragma unroll
        for (int j = 0; j < 5; j++) {
            R[j] = __shfl_down_sync(FULL, a[j].x, 1);
            L[j] = __shfl_up_sync(FULL, a[j].y, 1);
            if (isR) R[j] = b[j];
            if (isL) L[j] = b[j];
        }
#pragma unroll
        for (int r = 0; r < 4; r++) {
            float c0 = a[r].x, c1 = a[r].y;
            float n0 = a[r + 1].x, n1 = a[r + 1].y;
            aE[r].x  += fabsf(c0 - c1);
            aE[r].y  += fabsf(c1 - R[r]);
            aSW[r].x += fabsf(c0 - L[r + 1]);
            aSW[r].y += fabsf(c1 - n0);
            aS[r].x  += fabsf(c0 - n0);
            aS[r].y  += fabsf(c1 - n1);
            aSE[r].x += fabsf(c0 - n1);
            aSE[r].y += fabsf(c1 - R[r + 1]);
        }
    }

    const float inv = 1.0f / (float)NPLANES;
    float* sc = g_scratch + (size_t)seg * 4 * NN;
#pragma unroll
    for (int r = 0; r < 4; r++) {
        int o = (y0 + r) * WW + x0;
        *(float2*)(sc + 0 * NN + o) = make_float2(aE[r].x * inv,  aE[r].y * inv);
        *(float2*)(sc + 1 * NN + o) = make_float2(aSW[r].x * inv, aSW[r].y * inv);
        *(float2*)(sc + 2 * NN + o) = make_float2(aS[r].x * inv,  aS[r].y * inv);
        *(float2*)(sc + 3 * NN + o) = make_float2(aSE[r].x * inv, aSE[r].y * inv);
    }
}

// ---------------------------------------------------------------------------
// Transpose role: NCHW -> (B*H*W, C) via smem staging, fully coalesced.
// ---------------------------------------------------------------------------
__device__ __forceinline__ void trans_role(int tb, int t, float* s,
                                           const float* __restrict__ in,
                                           float* __restrict__ out) {
    int b  = tb >> 10;                 // 1024 blocks per batch image
    int p0 = (tb & 1023) * 256;

    const float* src = in + (size_t)b * CC * NN + p0 + t;
#pragma unroll
    for (int c = 0; c < CC; c++)
        s[c * TP + t] = src[(size_t)c * NN];
    __syncthreads();

    float4* o = (float4*)(out + ((size_t)b * NN + p0) * CC);
    int ch = (t & 3) * 4;
#pragma unroll
    for (int i = 0; i < 4; i++) {
        int px = i * 64 + (t >> 2);
        o[i * 256 + t] = make_float4(s[(ch + 0) * TP + px],
                                     s[(ch + 1) * TP + px],
                                     s[(ch + 2) * TP + px],
                                     s[(ch + 3) * TP + px]);
    }
}

// ---------------------------------------------------------------------------
// Fused phaseA + transpose: both read the same 64MB grid, mutually
// independent. A blocks first so all start in wave 1.
// ---------------------------------------------------------------------------
__global__ void __launch_bounds__(256, 4) fusedAT_kernel(const float* __restrict__ grid,
                                                         float* __restrict__ nf) {
    __shared__ float s[CC * TP];
    int bid = blockIdx.x;
    int t = threadIdx.x;

    if (bid < A_BLOCKS) {
        phaseA_role(bid, t, grid);
    } else {
        trans_role(bid - A_BLOCKS, t, s, grid, nf);
    }
}

// ---------------------------------------------------------------------------
// Phase B: edge-major emission, one thread per directed edge slot. Slot ->
// (x, dir) via analytic inversion + packed nibble LUTs. Sums NSEG segments.
// All output stores perfectly dense.
// ---------------------------------------------------------------------------
__global__ void __launch_bounds__(1024) phaseB_kernel(float* __restrict__ eio,
                                                      float2* __restrict__ attr) {
    int y = blockIdx.y;
    int o = blockIdx.x * 1024 + threadIdx.x;

    bool top = (y == 0), bot = (y == HH - 1);
    int rowcnt = (top || bot) ? 2556 : 4090;
    if (o >= rowcnt) return;
    int base = top ? 0 : 2556 + (y - 1) * 4090;

    int x, kk;
    unsigned lut;
    if (top || bot) {
        x = (o < 3) ? 0 : (o + 2) / 5;
        int ps = (x == 0) ? 0 : 5 * x - 2;
        kk = o - ps;
        if (top) lut = (x == 0) ? 0x764u : (x == WW - 1) ? 0x653u : 0x76543u;
        else     lut = (x == 0) ? 0x421u : (x == WW - 1) ? 0x310u : 0x43210u;
    } else {
        x = min((o + 3) >> 3, WW - 1);
        int ps = (x == 0) ? 0 : 8 * x - 3;
        kk = o - ps;
        lut = (x == 0) ? 0x76421u : (x == WW - 1) ? 0x65310u : 0x76543210u;
    }

    int dir = (lut >> (4 * kk)) & 0xF;          // _OFFSETS index 0..7
    int k2  = dir + (dir >= 4);                 // 0..8 grid position
    int dh  = k2 / 3 - 1;
    int dw  = k2 - (dh + 1) * 3 - 1;

    int p = y * WW + x;
    int q = p + dh * WW + dw;
    float dist = (dh * dw != 0) ? 1.41421356237309515f : 1.0f;

    // forward dirs read own pixel's array; backward read opposite dir at q
    int arr = (dir >= 4) ? (dir - 4) : (3 - dir);
    int loc = (dir >= 4) ? p : q;

    float f = 0.f;
#pragma unroll
    for (int s = 0; s < NSEG; s++)
        f += g_scratch[(size_t)s * 4 * NN + arr * NN + loc];

    int e = base + o;
    eio[e]         = (float)p;
    eio[E_CNT + e] = (float)q;
    attr[e] = make_float2(dist, f);
}

// ---------------------------------------------------------------------------
extern "C" void kernel_launch(void* const* d_in, const int* in_sizes, int n_in,
                              void* d_out, int out_size) {
    const float* grid = (const float*)d_in[0];

    float* out   = (float*)d_out;
    float* nf    = out;
    float* eio   = out + (size_t)BB * NN * CC;
    float2* attr = (float2*)(eio + 2 * E_CNT);

    fusedAT_kernel<<<A_BLOCKS + TRANS_BLOCKS, 256>>>(grid, nf);
    phaseB_kernel<<<dim3(4, HH), 1024>>>(eio, attr);
}

// round 15
// speedup vs baseline: 1.6751x; 1.0585x over previous
#include <cuda_runtime.h>
#include <cstddef>

// Fixed shapes: B=4, C=16, H=W=512
#define BB 4
#define CC 16
#define HH 512
#define WW 512
#define NN (HH * WW)
#define NPLANES (BB * CC)       // 64
#define E_CNT 2091012

#define TP 258                  // transpose smem pitch (conflict-free)

#define NSEG 4
#define PLANES_PER_SEG (NPLANES / NSEG)   // 16

#define A_BLOCKS_PER_SEG 128    // 128 blocks x 8 warps = 1024 warps per seg
#define A_BLOCKS (NSEG * A_BLOCKS_PER_SEG)   // 512
#define TRANS_BLOCKS 4096

#define BP 513                  // phaseB smem row pitch (odd -> conflict-free)

// 16 MB scratch: [seg][dir][y][x], dir: 0=E,1=SW,2=S,3=SE (pre-scaled by 1/64)
__device__ float g_scratch[NSEG * 4 * NN];

// ---------------------------------------------------------------------------
// Phase A role: forward diffs (E, SW, S, SE) per pixel over this segment's
// 16 planes, written DENSE to scratch. Warp = 64 cols (float2 lanes) x 4
// rows; 5 rows per plane, 1 plane per iteration (10 independent LDGs).
// ---------------------------------------------------------------------------
__device__ __forceinline__ void phaseA_role(int ab, int tid,
                                            const float* __restrict__ grid) {
    const unsigned FULL = 0xffffffffu;
    int lane = tid & 31;
    int seg  = ab >> 7;                       // 128 blocks per seg
    int warp = (ab & 127) * 8 + (tid >> 5);   // 0..1023 within seg

    int cchunk = warp & 7;           // 8 chunks of 64 cols
    int rchunk = warp >> 3;          // 128 chunks of 4 rows
    int cx = cchunk * 64;
    int y0 = rchunk * 4;
    int x0 = cx + lane * 2;

    bool isL = (lane == 0), isR = (lane == 31);
    bool bl  = isL || isR;
    int xb   = isL ? max(cx - 1, 0) : min(cx + 64, WW - 1);

    int ro[5];
#pragma unroll
    for (int j = 0; j < 5; j++) ro[j] = min(y0 + j, HH - 1) * WW;

    float2 aE[4], aSW[4], aS[4], aSE[4];
#pragma unroll
    for (int r = 0; r < 4; r++) {
        aE[r] = aSW[r] = aS[r] = aSE[r] = make_float2(0.f, 0.f);
    }

    const float* gseg = grid + (size_t)seg * PLANES_PER_SEG * NN;

    for (int g = 0; g < PLANES_PER_SEG; g++) {
        const float* p0 = gseg + (size_t)g * NN;

        float2 a[5];
        float  b[5];
#pragma unroll
        for (int j = 0; j < 5; j++)
            a[j] = *(const float2*)(p0 + ro[j] + x0);
#pragma unroll
        for (int j = 0; j < 5; j++)
            if (bl) b[j] = p0[ro[j] + xb];

        float L[5], R[5];
#pragma unroll
        for (int j = 0; j < 5; j++) {
            R[j] = __shfl_down_sync(FULL, a[j].x, 1);
            L[j] = __shfl_up_sync(FULL, a[j].y, 1);
            if (isR) R[j] = b[j];
            if (isL) L[j] = b[j];
        }
#pragma unroll
        for (int r = 0; r < 4; r++) {
            float c0 = a[r].x, c1 = a[r].y;
            float n0 = a[r + 1].x, n1 = a[r + 1].y;
            aE[r].x  += fabsf(c0 - c1);
            aE[r].y  += fabsf(c1 - R[r]);
            aSW[r].x += fabsf(c0 - L[r + 1]);
            aSW[r].y += fabsf(c1 - n0);
            aS[r].x  += fabsf(c0 - n0);
            aS[r].y  += fabsf(c1 - n1);
            aSE[r].x += fabsf(c0 - n1);
            aSE[r].y += fabsf(c1 - R[r + 1]);
        }
    }

    const float inv = 1.0f / (float)NPLANES;
    float* sc = g_scratch + (size_t)seg * 4 * NN;
#pragma unroll
    for (int r = 0; r < 4; r++) {
        int o = (y0 + r) * WW + x0;
        *(float2*)(sc + 0 * NN + o) = make_float2(aE[r].x * inv,  aE[r].y * inv);
        *(float2*)(sc + 1 * NN + o) = make_float2(aSW[r].x * inv, aSW[r].y * inv);
        *(float2*)(sc + 2 * NN + o) = make_float2(aS[r].x * inv,  aS[r].y * inv);
        *(float2*)(sc + 3 * NN + o) = make_float2(aSE[r].x * inv, aSE[r].y * inv);
    }
}

// ---------------------------------------------------------------------------
// Transpose role: NCHW -> (B*H*W, C) via smem staging, fully coalesced.
// ---------------------------------------------------------------------------
__device__ __forceinline__ void trans_role(int tb, int t, float* s,
                                           const float* __restrict__ in,
                                           float* __restrict__ out) {
    int b  = tb >> 10;                 // 1024 blocks per batch image
    int p0 = (tb & 1023) * 256;

    const float* src = in + (size_t)b * CC * NN + p0 + t;
#pragma unroll
    for (int c = 0; c < CC; c++)
        s[c * TP + t] = src[(size_t)c * NN];
    __syncthreads();

    float4* o = (float4*)(out + ((size_t)b * NN + p0) * CC);
    int ch = (t & 3) * 4;
#pragma unroll
    for (int i = 0; i < 4; i++) {
        int px = i * 64 + (t >> 2);
        o[i * 256 + t] = make_float4(s[(ch + 0) * TP + px],
                                     s[(ch + 1) * TP + px],
                                     s[(ch + 2) * TP + px],
                                     s[(ch + 3) * TP + px]);
    }
}

// ---------------------------------------------------------------------------
// Fused phaseA + transpose: both read the same 64MB grid, mutually
// independent. A blocks first so all start in wave 1.
// ---------------------------------------------------------------------------
__global__ void __launch_bounds__(256, 4) fusedAT_kernel(const float* __restrict__ grid,
                                                         float* __restrict__ nf) {
    __shared__ float s[CC * TP];
    int bid = blockIdx.x;
    int t = threadIdx.x;

    if (bid < A_BLOCKS) {
        phaseA_role(bid, t, grid);
    } else {
        trans_role(bid - A_BLOCKS, t, s, grid, nf);
    }
}

// ---------------------------------------------------------------------------
// Phase B: one block per row y. Stage the 7 scratch rows any edge of row y
// can touch (E,SW,S,SE at y; SW,S,SE at y-1) into smem with COALESCED loads
// (summing the NSEG segments during the load), then per-slot LDS + dense
// stores. smem id map: 0..3 = E,SW,S,SE @ y ; 4,5,6 = SW,S,SE @ y-1.
//   dir0 -> id6[x-1], dir1 -> id5[x], dir2 -> id4[x+1], dir3 -> id0[x-1],
//   dir4..7 -> id(dir-4)[x]
// ---------------------------------------------------------------------------
__global__ void __launch_bounds__(1024) phaseB_kernel(float* __restrict__ eio,
                                                      float2* __restrict__ attr) {
    __shared__ float s[7 * BP];

    int y = blockIdx.x;
    int t = threadIdx.x;

    // ---- cooperative staging: 7 * 512 elements, each = sum of NSEG segs ----
#pragma unroll
    for (int k = 0; k < 4; k++) {
        int i = k * 1024 + t;
        if (i < 7 * WW) {
            int j  = i >> 9;             // array id 0..6
            int xx = i & (WW - 1);
            int d  = (j < 4) ? j : (j - 3);
            int yy = (j < 4) ? y : (y - 1);
            float v = 0.f;
            if (yy >= 0) {
                int o = d * NN + yy * WW + xx;
#pragma unroll
                for (int sg = 0; sg < NSEG; sg++)
                    v += g_scratch[(size_t)sg * 4 * NN + o];
            }
            s[j * BP + xx] = v;
        }
    }
    __syncthreads();

    bool top = (y == 0), bot = (y == HH - 1);
    int rowcnt = (top || bot) ? 2556 : 4090;
    int base = top ? 0 : 2556 + (y - 1) * 4090;

    // per-dir smem (array id, dx) tables, packed as nibbles (low nibble = dir 0):
    // id:   {6,5,4,0,0,1,2,3} -> 0x32100456
    // dx+1: {0,1,2,0,1,1,1,1} -> 0x11110210   (FIXED: was 0x11111020)
    const unsigned ID_LUT = 0x32100456u;
    const unsigned DX_LUT = 0x11110210u;

#pragma unroll
    for (int k = 0; k < 4; k++) {
        int o = k * 1024 + t;
        if (o >= rowcnt) break;

        int x, kk;
        unsigned lut;
        if (top || bot) {
            x = (o < 3) ? 0 : (o + 2) / 5;
            int ps = (x == 0) ? 0 : 5 * x - 2;
            kk = o - ps;
            if (top) lut = (x == 0) ? 0x764u : (x == WW - 1) ? 0x653u : 0x76543u;
            else     lut = (x == 0) ? 0x421u : (x == WW - 1) ? 0x310u : 0x43210u;
        } else {
            x = min((o + 3) >> 3, WW - 1);
            int ps = (x == 0) ? 0 : 8 * x - 3;
            kk = o - ps;
            lut = (x == 0) ? 0x76421u : (x == WW - 1) ? 0x65310u : 0x76543210u;
        }

        int dir = (lut >> (4 * kk)) & 0xF;          // _OFFSETS index 0..7
        int k2  = dir + (dir >= 4);                 // 0..8 grid position
        int dh  = k2 / 3 - 1;
        int dw  = k2 - (dh + 1) * 3 - 1;

        int p = y * WW + x;
        int q = p + dh * WW + dw;
        float dist = (dh * dw != 0) ? 1.41421356237309515f : 1.0f;

        int id = (ID_LUT >> (4 * dir)) & 0xF;
        int dx = (int)((DX_LUT >> (4 * dir)) & 0xF) - 1;
        float f = s[id * BP + x + dx];

        int e = base + o;
        eio[e]         = (float)p;
        eio[E_CNT + e] = (float)q;
        attr[e] = make_float2(dist, f);
    }
}

// ---------------------------------------------------------------------------
extern "C" void kernel_launch(void* const* d_in, const int* in_sizes, int n_in,
                              void* d_out, int out_size) {
    const float* grid = (const float*)d_in[0];

    float* out   = (float*)d_out;
    float* nf    = out;
    float* eio   = out + (size_t)BB * NN * CC;
    float2* attr = (float2*)(eio + 2 * E_CNT);

    fusedAT_kernel<<<A_BLOCKS + TRANS_BLOCKS, 256>>>(grid, nf);
    phaseB_kernel<<<HH, 1024>>>(eio, attr);
}

// round 16
// speedup vs baseline: 1.7478x; 1.0434x over previous
#include <cuda_runtime.h>
#include <cstddef>

// Fixed shapes: B=4, C=16, H=W=512
#define BB 4
#define CC 16
#define HH 512
#define WW 512
#define NN (HH * WW)
#define NPLANES (BB * CC)       // 64
#define E_CNT 2091012

#define TP 258                  // transpose smem pitch (conflict-free)

#define NSEG 2
#define PLANES_PER_SEG (NPLANES / NSEG)   // 32

#define A_BLOCKS_PER_SEG 128    // 128 blocks x 8 warps = 1024 warps per seg
#define A_BLOCKS (NSEG * A_BLOCKS_PER_SEG)   // 256
#define TRANS_BLOCKS 4096

#define BP 513                  // phaseB smem row pitch (odd -> conflict-free)

// 8 MB scratch: [seg][dir][y][x], dir: 0=E,1=SW,2=S,3=SE (pre-scaled by 1/64)
__device__ float g_scratch[NSEG * 4 * NN];

// ---------------------------------------------------------------------------
// Phase A role: forward diffs (E, SW, S, SE) per pixel over this segment's
// planes, written DENSE to scratch. Warp = 64 cols (float2 lanes) x 4 rows;
// 5 rows per plane, 1 plane per iteration (10 independent LDGs).
// ---------------------------------------------------------------------------
__device__ __forceinline__ void phaseA_role(int ab, int tid,
                                            const float* __restrict__ grid) {
    const unsigned FULL = 0xffffffffu;
    int lane = tid & 31;
    int seg  = ab >> 7;                       // 128 blocks per seg
    int warp = (ab & 127) * 8 + (tid >> 5);   // 0..1023 within seg

    int cchunk = warp & 7;           // 8 chunks of 64 cols
    int rchunk = warp >> 3;          // 128 chunks of 4 rows
    int cx = cchunk * 64;
    int y0 = rchunk * 4;
    int x0 = cx + lane * 2;

    bool isL = (lane == 0), isR = (lane == 31);
    bool bl  = isL || isR;
    int xb   = isL ? max(cx - 1, 0) : min(cx + 64, WW - 1);

    int ro[5];
#pragma unroll
    for (int j = 0; j < 5; j++) ro[j] = min(y0 + j, HH - 1) * WW;

    float2 aE[4], aSW[4], aS[4], aSE[4];
#pragma unroll
    for (int r = 0; r < 4; r++) {
        aE[r] = aSW[r] = aS[r] = aSE[r] = make_float2(0.f, 0.f);
    }

    const float* gseg = grid + (size_t)seg * PLANES_PER_SEG * NN;

    for (int g = 0; g < PLANES_PER_SEG; g++) {
        const float* p0 = gseg + (size_t)g * NN;

        float2 a[5];
        float  b[5];
#pragma unroll
        for (int j = 0; j < 5; j++)
            a[j] = *(const float2*)(p0 + ro[j] + x0);
#pragma unroll
        for (int j = 0; j < 5; j++)
            if (bl) b[j] = p0[ro[j] + xb];

        float L[5], R[5];
#pragma unroll
        for (int j = 0; j < 5; j++) {
            R[j] = __shfl_down_sync(FULL, a[j].x, 1);
            L[j] = __shfl_up_sync(FULL, a[j].y, 1);
            if (isR) R[j] = b[j];
            if (isL) L[j] = b[j];
        }
#pragma unroll
        for (int r = 0; r < 4; r++) {
            float c0 = a[r].x, c1 = a[r].y;
            float n0 = a[r + 1].x, n1 = a[r + 1].y;
            aE[r].x  += fabsf(c0 - c1);
            aE[r].y  += fabsf(c1 - R[r]);
            aSW[r].x += fabsf(c0 - L[r + 1]);
            aSW[r].y += fabsf(c1 - n0);
            aS[r].x  += fabsf(c0 - n0);
            aS[r].y  += fabsf(c1 - n1);
            aSE[r].x += fabsf(c0 - n1);
            aSE[r].y += fabsf(c1 - R[r + 1]);
        }
    }

    const float inv = 1.0f / (float)NPLANES;
    float* sc = g_scratch + (size_t)seg * 4 * NN;
#pragma unroll
    for (int r = 0; r < 4; r++) {
        int o = (y0 + r) * WW + x0;
        *(float2*)(sc + 0 * NN + o) = make_float2(aE[r].x * inv,  aE[r].y * inv);
        *(float2*)(sc + 1 * NN + o) = make_float2(aSW[r].x * inv, aSW[r].y * inv);
        *(float2*)(sc + 2 * NN + o) = make_float2(aS[r].x * inv,  aS[r].y * inv);
        *(float2*)(sc + 3 * NN + o) = make_float2(aSE[r].x * inv, aSE[r].y * inv);
    }
}

// ---------------------------------------------------------------------------
// Transpose role: NCHW -> (B*H*W, C) via smem staging, fully coalesced.
// ---------------------------------------------------------------------------
__device__ __forceinline__ void trans_role(int tb, int t, float* s,
                                           const float* __restrict__ in,
                                           float* __restrict__ out) {
    int b  = tb >> 10;                 // 1024 blocks per batch image
    int p0 = (tb & 1023) * 256;

    const float* src = in + (size_t)b * CC * NN + p0 + t;
#pragma unroll
    for (int c = 0; c < CC; c++)
        s[c * TP + t] = src[(size_t)c * NN];
    __syncthreads();

    float4* o = (float4*)(out + ((size_t)b * NN + p0) * CC);
    int ch = (t & 3) * 4;
#pragma unroll
    for (int i = 0; i < 4; i++) {
        int px = i * 64 + (t >> 2);
        o[i * 256 + t] = make_float4(s[(ch + 0) * TP + px],
                                     s[(ch + 1) * TP + px],
                                     s[(ch + 2) * TP + px],
                                     s[(ch + 3) * TP + px]);
    }
}

// ---------------------------------------------------------------------------
// Fused phaseA + transpose: both read the same 64MB grid, mutually
// independent. A blocks first so all start in wave 1.
// ---------------------------------------------------------------------------
__global__ void __launch_bounds__(256, 4) fusedAT_kernel(const float* __restrict__ grid,
                                                         float* __restrict__ nf) {
    __shared__ float s[CC * TP];
    int bid = blockIdx.x;
    int t = threadIdx.x;

    if (bid < A_BLOCKS) {
        phaseA_role(bid, t, grid);
    } else {
        trans_role(bid - A_BLOCKS, t, s, grid, nf);
    }
}

// ---------------------------------------------------------------------------
// Phase B: one block per row y. Stage the 7 scratch rows any edge of row y
// can touch (E,SW,S,SE at y; SW,S,SE at y-1) into smem with COALESCED loads
// (summing the NSEG segments during the load), then per-slot LDS + dense
// stores. smem id map: 0..3 = E,SW,S,SE @ y ; 4,5,6 = SW,S,SE @ y-1.
//   dir0 -> id6[x-1], dir1 -> id5[x], dir2 -> id4[x+1], dir3 -> id0[x-1],
//   dir4..7 -> id(dir-4)[x]
// Interior-row fast path: x=(o+3)>>3, kk=(o+3)&7 is exact (slot range of x
// is [8x-3, 8x+5)); border-x folds into the same kk indexing via shifted
// LUT constants. dh=(dir>=3)+(dir>=5)-1; dw/dist via packed LUTs.
// ---------------------------------------------------------------------------
__global__ void __launch_bounds__(1024) phaseB_kernel(float* __restrict__ eio,
                                                      float2* __restrict__ attr) {
    __shared__ float s[7 * BP];

    int y = blockIdx.x;
    int t = threadIdx.x;

    // ---- cooperative staging: 7 * 512 elements, each = sum of NSEG segs ----
#pragma unroll
    for (int k = 0; k < 4; k++) {
        int i = k * 1024 + t;
        if (i < 7 * WW) {
            int j  = i >> 9;             // array id 0..6
            int xx = i & (WW - 1);
            int d  = (j < 4) ? j : (j - 3);
            int yy = (j < 4) ? y : (y - 1);
            float v = 0.f;
            if (yy >= 0) {
                int o = d * NN + yy * WW + xx;
#pragma unroll
                for (int sg = 0; sg < NSEG; sg++)
                    v += g_scratch[(size_t)sg * 4 * NN + o];
            }
            s[j * BP + xx] = v;
        }
    }
    __syncthreads();

    bool top = (y == 0), bot = (y == HH - 1);
    const float SQ2 = 1.41421356237309515f;

    // per-dir smem (array id, dx) tables, packed as nibbles (low nibble = dir 0):
    // id:   {6,5,4,0,0,1,2,3} -> 0x32100456
    // dx+1: {0,1,2,0,1,1,1,1} -> 0x11110210
    const unsigned ID_LUT = 0x32100456u;
    const unsigned DX_LUT = 0x11110210u;
    // dw+1 per dir: {0,1,2,0,2,0,1,2} -> 0x21020210 ; diagonal mask 0xA5
    const unsigned DW_LUT = 0x21020210u;

    if (!top && !bot) {
        int base = 2556 + (y - 1) * 4090;
#pragma unroll
        for (int k = 0; k < 4; k++) {
            int o = k * 1024 + t;
            if (o >= 4090) break;

            int o3 = o + 3;
            int kk = o3 & 7;
            int x  = min(o3 >> 3, WW - 1);
            unsigned lut = (x == 0) ? 0x76421000u
                         : (x == WW - 1) ? 0x65310u : 0x76543210u;

            int dir = (lut >> (4 * kk)) & 0xF;
            int dh  = (dir >= 3) + (dir >= 5) - 1;
            int dw  = (int)((DW_LUT >> (4 * dir)) & 0xF) - 1;

            int p = y * WW + x;
            int q = p + dh * WW + dw;
            float dist = ((0xA5u >> dir) & 1) ? SQ2 : 1.0f;

            int id = (ID_LUT >> (4 * dir)) & 0xF;
            int dx = (int)((DX_LUT >> (4 * dir)) & 0xF) - 1;
            float f = s[id * BP + x + dx];

            int e = base + o;
            eio[e]         = (float)p;
            eio[E_CNT + e] = (float)q;
            attr[e] = make_float2(dist, f);
        }
    } else {
        int base = top ? 0 : 2556 + (HH - 2) * 4090;
#pragma unroll
        for (int k = 0; k < 4; k++) {
            int o = k * 1024 + t;
            if (o >= 2556) break;

            int x = (o < 3) ? 0 : (o + 2) / 5;
            int ps = (x == 0) ? 0 : 5 * x - 2;
            int kk = o - ps;
            unsigned lut;
            if (top) lut = (x == 0) ? 0x764u : (x == WW - 1) ? 0x653u : 0x76543u;
            else     lut = (x == 0) ? 0x421u : (x == WW - 1) ? 0x310u : 0x43210u;

            int dir = (lut >> (4 * kk)) & 0xF;
            int dh  = (dir >= 3) + (dir >= 5) - 1;
            int dw  = (int)((DW_LUT >> (4 * dir)) & 0xF) - 1;

            int p = y * WW + x;
            int q = p + dh * WW + dw;
            float dist = ((0xA5u >> dir) & 1) ? SQ2 : 1.0f;

            int id = (ID_LUT >> (4 * dir)) & 0xF;
            int dx = (int)((DX_LUT >> (4 * dir)) & 0xF) - 1;
            float f = s[id * BP + x + dx];

            int e = base + o;
            eio[e]         = (float)p;
            eio[E_CNT + e] = (float)q;
            attr[e] = make_float2(dist, f);
        }
    }
}

// ---------------------------------------------------------------------------
extern "C" void kernel_launch(void* const* d_in, const int* in_sizes, int n_in,
                              void* d_out, int out_size) {
    const float* grid = (const float*)d_in[0];

    float* out   = (float*)d_out;
    float* nf    = out;
    float* eio   = out + (size_t)BB * NN * CC;
    float2* attr = (float2*)(eio + 2 * E_CNT);

    fusedAT_kernel<<<A_BLOCKS + TRANS_BLOCKS, 256>>>(grid, nf);
    phaseB_kernel<<<HH, 1024>>>(eio, attr);
}